// round 12
// baseline (speedup 1.0000x reference)
#include <cuda_runtime.h>
#include <cuda_bf16.h>
#include <math.h>
#include <stdint.h>

#define N_ROWS 4096
#define D_DIM  2048
#define V_DIM  32000
#define SOFTCAP 30.0f

#define BM 128
#define BN 256
#define BK 64
#define STAGES 4
#define NIT (D_DIM / BK)          // 32 k-iterations

#define STG  (48 * 1024)          // bytes per stage: A 16KB + B 32KB
#define BOFF (16 * 1024)          // B offset within a stage
#define SMEM_TOTAL (STAGES * STG) // 192KB dynamic

// ---------------- device scratch ----------------
__device__ __nv_bfloat16 g_Wt[(size_t)V_DIM * D_DIM];   // [v][d] K-major bf16
__device__ __nv_bfloat16 g_A [(size_t)N_ROWS * D_DIM];  // [n][d] bf16
__device__ float g_sumexp[N_ROWS];
__device__ float g_sumlog[N_ROWS];
__device__ float g_tgt  [N_ROWS];
__device__ int   g_is64;

// ---------------- PTX helpers ----------------
__device__ __forceinline__ uint32_t smem_u32(const void* p) {
    uint32_t a;
    asm("{ .reg .u64 t; cvta.to.shared.u64 t, %1; cvt.u32.u64 %0, t; }" : "=r"(a) : "l"(p));
    return a;
}
__device__ __forceinline__ void cp16(uint32_t s, const void* g) {
    asm volatile("cp.async.cg.shared.global [%0], [%1], 16;" :: "r"(s), "l"(g));
}
#define CP_COMMIT() asm volatile("cp.async.commit_group;" ::: "memory")
#define CP_WAIT2()  asm volatile("cp.async.wait_group 2;" ::: "memory")

#define LDSM_X4(r, a) \
    asm volatile("ldmatrix.sync.aligned.m8n8.x4.shared.b16 {%0,%1,%2,%3}, [%4];" \
        : "=r"((r)[0]), "=r"((r)[1]), "=r"((r)[2]), "=r"((r)[3]) : "r"(a))

__device__ __forceinline__ void mma_bf16(float* c, const unsigned* a, const unsigned* b) {
    asm volatile(
        "mma.sync.aligned.m16n8k16.row.col.f32.bf16.bf16.f32 "
        "{%0,%1,%2,%3}, {%4,%5,%6,%7}, {%8,%9}, {%0,%1,%2,%3};\n"
        : "+f"(c[0]), "+f"(c[1]), "+f"(c[2]), "+f"(c[3])
        : "r"(a[0]), "r"(a[1]), "r"(a[2]), "r"(a[3]), "r"(b[0]), "r"(b[1]));
}

// ---------------- math helpers ----------------
__device__ __forceinline__ float softcap_f(float x) {
    float z = fabsf(x) * (2.0f / SOFTCAP);
    float e = __expf(-z);
    float t = (1.0f - e) / (1.0f + e);
    return copysignf(SOFTCAP * t, x);
}
__device__ __forceinline__ long long get_target(const void* t, int i) {
    return g_is64 ? ((const long long*)t)[i] : (long long)((const int*)t)[i];
}

// ---------------- setup: zero accumulators + dtype detection (race-free) ----------------
__global__ void setup_kernel(const void* __restrict__ t) {
    int i = blockIdx.x * blockDim.x + threadIdx.x;
    if (i < N_ROWS) { g_sumexp[i] = 0.f; g_sumlog[i] = 0.f; g_tgt[i] = 0.f; }
    if (blockIdx.x == 0) {
        __shared__ int s_not64;
        if (threadIdx.x == 0) s_not64 = 0;
        __syncthreads();
        const unsigned long long* p = (const unsigned long long*)t;
        int bad = 0;
        for (int j = threadIdx.x; j < N_ROWS / 2; j += blockDim.x) {
            unsigned hi = (unsigned)(p[j] >> 32);
            if (hi != 0u && hi != 0xFFFFFFFFu) bad = 1;
        }
        if (bad) atomicExch(&s_not64, 1);
        __syncthreads();
        if (threadIdx.x == 0) g_is64 = s_not64 ? 0 : 1;
    }
}

__global__ void convertA(const float* __restrict__ in) {
    int i = blockIdx.x * blockDim.x + threadIdx.x;
    float4 f = ((const float4*)in)[i];
    __nv_bfloat162* o = (__nv_bfloat162*)g_A;
    o[2 * i]     = __floats2bfloat162_rn(f.x, f.y);
    o[2 * i + 1] = __floats2bfloat162_rn(f.z, f.w);
}
__global__ void transposeW(const float* __restrict__ W) {
    __shared__ __nv_bfloat16 tl[32][33];
    int tx = threadIdx.x, ty = threadIdx.y;
    int bv = blockIdx.x * 32, bd = blockIdx.y * 32;
#pragma unroll
    for (int j = 0; j < 4; j++)
        tl[ty + j * 8][tx] = __float2bfloat16(W[(size_t)(bd + ty + j * 8) * V_DIM + bv + tx]);
    __syncthreads();
#pragma unroll
    for (int j = 0; j < 4; j++)
        g_Wt[(size_t)(bv + ty + j * 8) * D_DIM + bd + tx] = tl[tx][ty + j * 8];
}

// ---------------- pipelined mma.sync GEMM: 8 warps, 64x64 tiles, frag double-buffer ----------------
__global__ void __launch_bounds__(256, 1) gemm_pipe(const void* __restrict__ targets) {
    extern __shared__ char smem[];
    __shared__ float s_se[BM];
    __shared__ float s_sl[BM];
    const uint32_t sbase = smem_u32(smem);

    const int tid  = threadIdx.x;
    const int lane = tid & 31, wid = tid >> 5;
    const int wm = wid >> 2, wn = wid & 3;        // 2x4 warp grid; warp tile 64(m) x 64(n)
    const int g  = lane >> 2, tg = lane & 3;
    const int bm0 = blockIdx.x * BM;
    const int bn0 = blockIdx.y * BN;

    if (tid < BM) { s_se[tid] = 0.f; s_sl[tid] = 0.f; }

    const __nv_bfloat16* Ag = g_A  + (size_t)bm0 * D_DIM;
    const __nv_bfloat16* Bg = g_Wt + (size_t)bn0 * D_DIM;
    // 256 threads: 32 row-groups x 8 chunk-cols; swizzle chunk ^= row&7
    const int arow0 = tid >> 3, ac = tid & 7;

    // ldmatrix bases
    const int rA = wm * 64 + (lane & 15);                      // + mt*16
    const int aSw = rA & 7;
    const int aHalf = lane >> 4;                               // k 16B-chunk select
    const int rB = wn * 64 + (lane & 7) + ((lane >> 4) << 3);  // + p*16
    const int bSw = lane & 7;
    const int bHalf = (lane >> 3) & 1;

    float acc[4][8][4];
#pragma unroll
    for (int mt = 0; mt < 4; mt++)
#pragma unroll
        for (int nt = 0; nt < 8; nt++)
#pragma unroll
            for (int r = 0; r < 4; r++) acc[mt][nt][r] = 0.f;

    // prologue: fill stages 0..2 (A 4 cps + B 8 cps per thread per stage)
#pragma unroll
    for (int s = 0; s < STAGES - 1; s++) {
        uint32_t la = sbase + s * STG;
        const __nv_bfloat16* ap = Ag + s * BK;
        const __nv_bfloat16* bp = Bg + s * BK;
#pragma unroll
        for (int j = 0; j < 4; j++) {
            int row = arow0 + j * 32;
            cp16(la + row * 128 + ((ac ^ (row & 7)) << 4), ap + (size_t)row * D_DIM + ac * 8);
        }
#pragma unroll
        for (int j = 0; j < 8; j++) {
            int row = arow0 + j * 32;
            cp16(la + BOFF + row * 128 + ((ac ^ (row & 7)) << 4), bp + (size_t)row * D_DIM + ac * 8);
        }
        CP_COMMIT();
    }

#pragma unroll 1
    for (int i = 0; i < NIT; i++) {
        CP_WAIT2();
        __syncthreads();

        const int nf = i + STAGES - 1;
        const bool dl = nf < NIT;
        uint32_t la = sbase + (nf & 3) * STG;
        const __nv_bfloat16* ap = Ag + nf * BK;
        const __nv_bfloat16* bp = Bg + nf * BK;

        // A-prefetch for stage nf (4 cps), up-front
        if (dl) {
#pragma unroll
            for (int j = 0; j < 4; j++) {
                int row = arow0 + j * 32;
                cp16(la + row * 128 + ((ac ^ (row & 7)) << 4), ap + (size_t)row * D_DIM + ac * 8);
            }
        }

        uint32_t sa = sbase + (i & 3) * STG;
        uint32_t sb = sa + BOFF;

        // double-buffered fragments: LDSM(ks+1) issued before MMA(ks)
        unsigned af[2][4][4], bf[2][4][4];
#pragma unroll
        for (int mt = 0; mt < 4; mt++)
            LDSM_X4(af[0][mt], sa + (rA + mt * 16) * 128 + ((aHalf ^ aSw) << 4));
#pragma unroll
        for (int p = 0; p < 4; p++)
            LDSM_X4(bf[0][p], sb + (rB + p * 16) * 128 + ((bHalf ^ bSw) << 4));

#pragma unroll
        for (int ks = 0; ks < 4; ks++) {
            const int cur = ks & 1, nxt = cur ^ 1;
            if (ks < 3) {
#pragma unroll
                for (int mt = 0; mt < 4; mt++)
                    LDSM_X4(af[nxt][mt], sa + (rA + mt * 16) * 128 + (((2 * (ks + 1) + aHalf) ^ aSw) << 4));
#pragma unroll
                for (int p = 0; p < 4; p++)
                    LDSM_X4(bf[nxt][p], sb + (rB + p * 16) * 128 + (((2 * (ks + 1) + bHalf) ^ bSw) << 4));
            }
            // 2 B cps per ks: spread cp.async pressure across the stage
            if (dl) {
#pragma unroll
                for (int j = 0; j < 2; j++) {
                    int row = arow0 + (ks * 2 + j) * 32;
                    cp16(la + BOFF + row * 128 + ((ac ^ (row & 7)) << 4), bp + (size_t)row * D_DIM + ac * 8);
                }
            }
#pragma unroll
            for (int mt = 0; mt < 4; mt++)
#pragma unroll
                for (int nt = 0; nt < 8; nt++)
                    mma_bf16(acc[mt][nt], af[cur][mt], &bf[cur][nt >> 1][(nt & 1) * 2]);
        }
        CP_COMMIT();
    }
    __syncthreads();

    // -------- fused epilogue: softcap + per-row {sum exp(l-30), sum l, target logit} --------
#pragma unroll
    for (int mt = 0; mt < 4; mt++) {
        int r0 = wm * 64 + mt * 16 + g;
        int r1 = r0 + 8;
        long long t0 = get_target(targets, bm0 + r0);
        long long t1 = get_target(targets, bm0 + r1);
        int tc0 = (int)(t0 - (long long)bn0);
        int tc1 = (int)(t1 - (long long)bn0);
        float se0 = 0.f, sl0 = 0.f, se1 = 0.f, sl1 = 0.f;
#pragma unroll
        for (int nt = 0; nt < 8; nt++) {
            int c0 = wn * 64 + nt * 8 + tg * 2;
            float l00 = softcap_f(acc[mt][nt][0]);
            float l01 = softcap_f(acc[mt][nt][1]);
            float l10 = softcap_f(acc[mt][nt][2]);
            float l11 = softcap_f(acc[mt][nt][3]);
            se0 += __expf(l00 - SOFTCAP) + __expf(l01 - SOFTCAP);
            sl0 += l00 + l01;
            se1 += __expf(l10 - SOFTCAP) + __expf(l11 - SOFTCAP);
            sl1 += l10 + l11;
            if (c0     == tc0) g_tgt[bm0 + r0] = l00;
            if (c0 + 1 == tc0) g_tgt[bm0 + r0] = l01;
            if (c0     == tc1) g_tgt[bm0 + r1] = l10;
            if (c0 + 1 == tc1) g_tgt[bm0 + r1] = l11;
        }
        se0 += __shfl_xor_sync(0xffffffffu, se0, 1); se0 += __shfl_xor_sync(0xffffffffu, se0, 2);
        sl0 += __shfl_xor_sync(0xffffffffu, sl0, 1); sl0 += __shfl_xor_sync(0xffffffffu, sl0, 2);
        se1 += __shfl_xor_sync(0xffffffffu, se1, 1); se1 += __shfl_xor_sync(0xffffffffu, se1, 2);
        sl1 += __shfl_xor_sync(0xffffffffu, sl1, 1); sl1 += __shfl_xor_sync(0xffffffffu, sl1, 2);
        if (tg == 0) {
            atomicAdd(&s_se[r0], se0); atomicAdd(&s_sl[r0], sl0);
            atomicAdd(&s_se[r1], se1); atomicAdd(&s_sl[r1], sl1);
        }
    }
    __syncthreads();
    if (tid < BM) {
        atomicAdd(&g_sumexp[bm0 + tid], s_se[tid]);
        atomicAdd(&g_sumlog[bm0 + tid], s_sl[tid]);
    }
}

__global__ void final_kernel(const void* __restrict__ targets, float* __restrict__ out) {
    __shared__ double ssum[256];
    __shared__ int    scnt[256];
    double acc = 0.0;
    int cnt = 0;
    for (int i = threadIdx.x; i < N_ROWS; i += 256) {
        long long t = get_target(targets, i);
        if (t != -100) {
            float lse = SOFTCAP + logf(g_sumexp[i]);
            float ce  = lse - 0.9f * g_tgt[i] - 0.1f * (g_sumlog[i] * (1.0f / (float)V_DIM));
            float z   = 1e-4f * lse * lse;
            acc += (double)(ce + z); cnt++;
        }
    }
    ssum[threadIdx.x] = acc; scnt[threadIdx.x] = cnt;
    __syncthreads();
    for (int s = 128; s > 0; s >>= 1) {
        if (threadIdx.x < s) { ssum[threadIdx.x] += ssum[threadIdx.x + s]; scnt[threadIdx.x] += scnt[threadIdx.x + s]; }
        __syncthreads();
    }
    if (threadIdx.x == 0) out[0] = (float)(ssum[0] / (double)scnt[0]);
}

// ---------------- launch ----------------
extern "C" void kernel_launch(void* const* d_in, const int* in_sizes, int n_in,
                              void* d_out, int out_size) {
    const float* input   = (const float*)d_in[0];
    const float* weight  = (const float*)d_in[1];
    const void*  targets = d_in[2];
    (void)in_sizes; (void)n_in; (void)out_size;

    cudaFuncSetAttribute(gemm_pipe, cudaFuncAttributeMaxDynamicSharedMemorySize, SMEM_TOTAL);

    // launch order keeps gemm_pipe in the ncu capture slot (#4)
    setup_kernel<<<(N_ROWS + 255) / 256, 256>>>(targets);
    convertA<<<(N_ROWS * D_DIM / 4) / 256, 256>>>(input);
    transposeW<<<dim3(V_DIM / 32, D_DIM / 32), dim3(32, 8)>>>(weight);
    gemm_pipe<<<dim3(N_ROWS / BM, V_DIM / BN), 256, SMEM_TOTAL>>>(targets);
    final_kernel<<<1, 256>>>(targets, (float*)d_out);
}

// round 14
// speedup vs baseline: 1.1803x; 1.1803x over previous
#include <cuda_runtime.h>
#include <cuda_bf16.h>
#include <math.h>
#include <stdint.h>

#define N_ROWS 4096
#define D_DIM  2048
#define V_DIM  32000
#define SOFTCAP 30.0f

#define BM 128
#define BN 128
#define BK 64
#define STAGES 3
#define NIT (D_DIM / BK)          // 32 k-iterations

#define STG  (32 * 1024)          // bytes per stage: A 16KB + B 16KB
#define BOFF (16 * 1024)          // B offset within a stage
#define SMEM_TOTAL (STAGES * STG) // 96KB dynamic -> 2 CTAs/SM

// ---------------- device scratch ----------------
__device__ __nv_bfloat16 g_Wt[(size_t)V_DIM * D_DIM];   // [v][d] K-major bf16
__device__ __nv_bfloat16 g_A [(size_t)N_ROWS * D_DIM];  // [n][d] bf16
__device__ float g_sumexp[N_ROWS];
__device__ float g_sumlog[N_ROWS];
__device__ float g_tgt  [N_ROWS];
__device__ int   g_is64;

// ---------------- PTX helpers ----------------
__device__ __forceinline__ uint32_t smem_u32(const void* p) {
    uint32_t a;
    asm("{ .reg .u64 t; cvta.to.shared.u64 t, %1; cvt.u32.u64 %0, t; }" : "=r"(a) : "l"(p));
    return a;
}
__device__ __forceinline__ void cp16(uint32_t s, const void* g) {
    asm volatile("cp.async.cg.shared.global [%0], [%1], 16;" :: "r"(s), "l"(g));
}
#define CP_COMMIT() asm volatile("cp.async.commit_group;" ::: "memory")
#define CP_WAIT1()  asm volatile("cp.async.wait_group 1;" ::: "memory")

#define LDSM_X4(r, a) \
    asm volatile("ldmatrix.sync.aligned.m8n8.x4.shared.b16 {%0,%1,%2,%3}, [%4];" \
        : "=r"((r)[0]), "=r"((r)[1]), "=r"((r)[2]), "=r"((r)[3]) : "r"(a))

__device__ __forceinline__ void mma_bf16(float* c, const unsigned* a, const unsigned* b) {
    asm volatile(
        "mma.sync.aligned.m16n8k16.row.col.f32.bf16.bf16.f32 "
        "{%0,%1,%2,%3}, {%4,%5,%6,%7}, {%8,%9}, {%0,%1,%2,%3};\n"
        : "+f"(c[0]), "+f"(c[1]), "+f"(c[2]), "+f"(c[3])
        : "r"(a[0]), "r"(a[1]), "r"(a[2]), "r"(a[3]), "r"(b[0]), "r"(b[1]));
}

// ---------------- math helpers ----------------
__device__ __forceinline__ float softcap_f(float x) {
    float z = fabsf(x) * (2.0f / SOFTCAP);
    float e = __expf(-z);
    float t = (1.0f - e) / (1.0f + e);
    return copysignf(SOFTCAP * t, x);
}
__device__ __forceinline__ long long get_target(const void* t, int i) {
    return g_is64 ? ((const long long*)t)[i] : (long long)((const int*)t)[i];
}

// ---------------- setup: zero accumulators + dtype detection (race-free) ----------------
__global__ void setup_kernel(const void* __restrict__ t) {
    int i = blockIdx.x * blockDim.x + threadIdx.x;
    if (i < N_ROWS) { g_sumexp[i] = 0.f; g_sumlog[i] = 0.f; g_tgt[i] = 0.f; }
    if (blockIdx.x == 0) {
        __shared__ int s_not64;
        if (threadIdx.x == 0) s_not64 = 0;
        __syncthreads();
        const unsigned long long* p = (const unsigned long long*)t;
        int bad = 0;
        for (int j = threadIdx.x; j < N_ROWS / 2; j += blockDim.x) {
            unsigned hi = (unsigned)(p[j] >> 32);
            if (hi != 0u && hi != 0xFFFFFFFFu) bad = 1;
        }
        if (bad) atomicExch(&s_not64, 1);
        __syncthreads();
        if (threadIdx.x == 0) g_is64 = s_not64 ? 0 : 1;
    }
}

__global__ void convertA(const float* __restrict__ in) {
    int i = blockIdx.x * blockDim.x + threadIdx.x;
    float4 f = ((const float4*)in)[i];
    __nv_bfloat162* o = (__nv_bfloat162*)g_A;
    o[2 * i]     = __floats2bfloat162_rn(f.x, f.y);
    o[2 * i + 1] = __floats2bfloat162_rn(f.z, f.w);
}
__global__ void transposeW(const float* __restrict__ W) {
    __shared__ __nv_bfloat16 tl[32][33];
    int tx = threadIdx.x, ty = threadIdx.y;
    int bv = blockIdx.x * 32, bd = blockIdx.y * 32;
#pragma unroll
    for (int j = 0; j < 4; j++)
        tl[ty + j * 8][tx] = __float2bfloat16(W[(size_t)(bd + ty + j * 8) * V_DIM + bv + tx]);
    __syncthreads();
#pragma unroll
    for (int j = 0; j < 4; j++)
        g_Wt[(size_t)(bv + ty + j * 8) * D_DIM + bd + tx] = tl[tx][ty + j * 8];
}

// ---------------- pipelined mma.sync GEMM: 2 CTAs/SM, 8 warps, 64x32 warp tiles ----------------
__global__ void __launch_bounds__(256, 2) gemm_pipe(const void* __restrict__ targets) {
    extern __shared__ char smem[];
    __shared__ float s_se[BM];
    __shared__ float s_sl[BM];
    const uint32_t sbase = smem_u32(smem);

    const int tid  = threadIdx.x;
    const int lane = tid & 31, wid = tid >> 5;
    const int wm = wid >> 2, wn = wid & 3;        // 2x4 warp grid; warp tile 64(m) x 32(n)
    const int g  = lane >> 2, tg = lane & 3;
    const int bm0 = blockIdx.x * BM;
    const int bn0 = blockIdx.y * BN;

    if (tid < BM) { s_se[tid] = 0.f; s_sl[tid] = 0.f; }

    const __nv_bfloat16* Ag = g_A  + (size_t)bm0 * D_DIM;
    const __nv_bfloat16* Bg = g_Wt + (size_t)bn0 * D_DIM;
    // 256 threads: 32 row-groups x 8 chunk-cols; swizzle chunk ^= row&7
    const int arow0 = tid >> 3, ac = tid & 7;

    // ldmatrix bases
    const int rA = wm * 64 + (lane & 15);                      // + mt*16
    const int aSw = rA & 7;
    const int aHalf = lane >> 4;                               // k 16B-chunk select
    const int rB = wn * 32 + (lane & 7) + ((lane >> 4) << 3);  // + p*16
    const int bSw = lane & 7;
    const int bHalf = (lane >> 3) & 1;

    float acc[4][4][4];
#pragma unroll
    for (int mt = 0; mt < 4; mt++)
#pragma unroll
        for (int nt = 0; nt < 4; nt++)
#pragma unroll
            for (int r = 0; r < 4; r++) acc[mt][nt][r] = 0.f;

#define LOAD_STAGE(s, ki) do { \
    uint32_t la_ = sbase + (s) * STG; \
    const __nv_bfloat16* ap_ = Ag + (ki) * BK; \
    const __nv_bfloat16* bp_ = Bg + (ki) * BK; \
    _Pragma("unroll") \
    for (int j = 0; j < 4; j++) { \
        int row = arow0 + j * 32; \
        cp16(la_ + row * 128 + (((ac) ^ (row & 7)) << 4), ap_ + (size_t)row * D_DIM + ac * 8); \
    } \
    _Pragma("unroll") \
    for (int j = 0; j < 4; j++) { \
        int row = arow0 + j * 32; \
        cp16(la_ + BOFF + row * 128 + (((ac) ^ (row & 7)) << 4), bp_ + (size_t)row * D_DIM + ac * 8); \
    } \
} while (0)

    // prologue: fill stages 0..1
#pragma unroll
    for (int s = 0; s < STAGES - 1; s++) { LOAD_STAGE(s, s); CP_COMMIT(); }

    int slot = 0;            // slot of iteration i
    int wslot = STAGES - 1;  // slot to write next
#pragma unroll 1
    for (int i = 0; i < NIT; i++) {
        CP_WAIT1();
        __syncthreads();

        const int nf = i + STAGES - 1;
        if (nf < NIT) LOAD_STAGE(wslot, nf);
        CP_COMMIT();

        uint32_t sa = sbase + slot * STG;
        uint32_t sb = sa + BOFF;
#pragma unroll
        for (int ks = 0; ks < 4; ks++) {
            unsigned af[4][4], bf[2][4];
#pragma unroll
            for (int mt = 0; mt < 4; mt++)
                LDSM_X4(af[mt], sa + (rA + mt * 16) * 128 + (((2 * ks + aHalf) ^ aSw) << 4));
#pragma unroll
            for (int p = 0; p < 2; p++)
                LDSM_X4(bf[p], sb + (rB + p * 16) * 128 + (((2 * ks + bHalf) ^ bSw) << 4));
#pragma unroll
            for (int mt = 0; mt < 4; mt++)
#pragma unroll
                for (int nt = 0; nt < 4; nt++)
                    mma_bf16(acc[mt][nt], af[mt], &bf[nt >> 1][(nt & 1) * 2]);
        }
        slot = (slot + 1 == STAGES) ? 0 : slot + 1;
        wslot = (wslot + 1 == STAGES) ? 0 : wslot + 1;
    }
    __syncthreads();

    // -------- fused epilogue: softcap + per-row {sum exp(l-30), sum l, target logit} --------
#pragma unroll
    for (int mt = 0; mt < 4; mt++) {
        int r0 = wm * 64 + mt * 16 + g;
        int r1 = r0 + 8;
        long long t0 = get_target(targets, bm0 + r0);
        long long t1 = get_target(targets, bm0 + r1);
        int tc0 = (int)(t0 - (long long)bn0);
        int tc1 = (int)(t1 - (long long)bn0);
        float se0 = 0.f, sl0 = 0.f, se1 = 0.f, sl1 = 0.f;
#pragma unroll
        for (int nt = 0; nt < 4; nt++) {
            int c0 = wn * 32 + nt * 8 + tg * 2;
            float l00 = softcap_f(acc[mt][nt][0]);
            float l01 = softcap_f(acc[mt][nt][1]);
            float l10 = softcap_f(acc[mt][nt][2]);
            float l11 = softcap_f(acc[mt][nt][3]);
            se0 += __expf(l00 - SOFTCAP) + __expf(l01 - SOFTCAP);
            sl0 += l00 + l01;
            se1 += __expf(l10 - SOFTCAP) + __expf(l11 - SOFTCAP);
            sl1 += l10 + l11;
            if (c0     == tc0) g_tgt[bm0 + r0] = l00;
            if (c0 + 1 == tc0) g_tgt[bm0 + r0] = l01;
            if (c0     == tc1) g_tgt[bm0 + r1] = l10;
            if (c0 + 1 == tc1) g_tgt[bm0 + r1] = l11;
        }
        se0 += __shfl_xor_sync(0xffffffffu, se0, 1); se0 += __shfl_xor_sync(0xffffffffu, se0, 2);
        sl0 += __shfl_xor_sync(0xffffffffu, sl0, 1); sl0 += __shfl_xor_sync(0xffffffffu, sl0, 2);
        se1 += __shfl_xor_sync(0xffffffffu, se1, 1); se1 += __shfl_xor_sync(0xffffffffu, se1, 2);
        sl1 += __shfl_xor_sync(0xffffffffu, sl1, 1); sl1 += __shfl_xor_sync(0xffffffffu, sl1, 2);
        if (tg == 0) {
            atomicAdd(&s_se[r0], se0); atomicAdd(&s_sl[r0], sl0);
            atomicAdd(&s_se[r1], se1); atomicAdd(&s_sl[r1], sl1);
        }
    }
    __syncthreads();
    if (tid < BM) {
        atomicAdd(&g_sumexp[bm0 + tid], s_se[tid]);
        atomicAdd(&g_sumlog[bm0 + tid], s_sl[tid]);
    }
}

__global__ void final_kernel(const void* __restrict__ targets, float* __restrict__ out) {
    __shared__ double ssum[256];
    __shared__ int    scnt[256];
    double acc = 0.0;
    int cnt = 0;
    for (int i = threadIdx.x; i < N_ROWS; i += 256) {
        long long t = get_target(targets, i);
        if (t != -100) {
            float lse = SOFTCAP + logf(g_sumexp[i]);
            float ce  = lse - 0.9f * g_tgt[i] - 0.1f * (g_sumlog[i] * (1.0f / (float)V_DIM));
            float z   = 1e-4f * lse * lse;
            acc += (double)(ce + z); cnt++;
        }
    }
    ssum[threadIdx.x] = acc; scnt[threadIdx.x] = cnt;
    __syncthreads();
    for (int s = 128; s > 0; s >>= 1) {
        if (threadIdx.x < s) { ssum[threadIdx.x] += ssum[threadIdx.x + s]; scnt[threadIdx.x] += scnt[threadIdx.x + s]; }
        __syncthreads();
    }
    if (threadIdx.x == 0) out[0] = (float)(ssum[0] / (double)scnt[0]);
}

// ---------------- launch ----------------
extern "C" void kernel_launch(void* const* d_in, const int* in_sizes, int n_in,
                              void* d_out, int out_size) {
    const float* input   = (const float*)d_in[0];
    const float* weight  = (const float*)d_in[1];
    const void*  targets = d_in[2];
    (void)in_sizes; (void)n_in; (void)out_size;

    cudaFuncSetAttribute(gemm_pipe, cudaFuncAttributeMaxDynamicSharedMemorySize, SMEM_TOTAL);

    // launch order keeps gemm_pipe in the ncu capture slot (#4)
    setup_kernel<<<(N_ROWS + 255) / 256, 256>>>(targets);
    convertA<<<(N_ROWS * D_DIM / 4) / 256, 256>>>(input);
    transposeW<<<dim3(V_DIM / 32, D_DIM / 32), dim3(32, 8)>>>(weight);
    gemm_pipe<<<dim3(N_ROWS / BM, V_DIM / BN), 256, SMEM_TOTAL>>>(targets);
    final_kernel<<<1, 256>>>(targets, (float*)d_out);
}